// round 12
// baseline (speedup 1.0000x reference)
#include <cuda_runtime.h>
#include <math.h>
#include <stdint.h>

#define NN   4096
#define EMBD 32
#define BQ   8192
#define KNN  20
#define FULL 0xffffffffu

typedef unsigned long long u64;
typedef unsigned int u32;

// Scratch (device globals; no allocation in kernel_launch)
__device__ float g_D2[(size_t)2 * NN * NN];    // 2 x 64 MB, one per branch
__device__ float g_bmin[2 * NN * 32];          // per-branch per-row tile mins
__device__ int   g_nbr_idx[2 * NN * KNN];
__device__ float g_nbr_d2[2 * NN * KNN];

// dynamic smem layout for knn_gemm
#define AS_OFF 0
#define BS_OFF 16896                            // 32*132*4
#define T_OFF  33792                            // + 32*132*4
#define NA_OFF 66560                            // + 64*128*4 (T)
#define NB_OFF 67072                            // + 128*4
#define SMEM_DYN 67584                          // + 128*4 = 66 KB

// ---------------------------------------------------------------------------
// packed f32x2 helpers (Blackwell FFMA2 path — PTX only)
// ---------------------------------------------------------------------------
__device__ __forceinline__ u64 pack2(float lo, float hi) {
    u64 r;
    asm("mov.b64 %0, {%1, %2};" : "=l"(r) : "f"(lo), "f"(hi));
    return r;
}
__device__ __forceinline__ void unpack2(u64 v, float& lo, float& hi) {
    asm("mov.b64 {%0, %1}, %2;" : "=f"(lo), "=f"(hi) : "l"(v));
}
__device__ __forceinline__ void ffma2(u64& d, u64 a, u64 b) {
    asm("fma.rn.f32x2 %0, %1, %2, %0;" : "+l"(d) : "l"(a), "l"(b));
}
__device__ __forceinline__ u64 addf2(u64 a, u64 b) {
    u64 r;
    asm("add.rn.f32x2 %0, %1, %2;" : "=l"(r) : "l"(a), "l"(b));
    return r;
}

// ---------------------------------------------------------------------------
// Upper-triangle all-pairs distances, both branches: grid (528, 2).
// Norms computed in-CTA (one per thread, from L1-hot emb data) into smem —
// no separate norms kernel. Two 64-column passes with acc[4][4] packed f32x2
// so 3 CTAs/SM fit. Mirror tile staged via dedicated swizzled smem region.
// ---------------------------------------------------------------------------
__global__ void __launch_bounds__(256, 3) knn_gemm(const float* __restrict__ emb1,
                                                   const float* __restrict__ emb2) {
    extern __shared__ char smraw[];
    float (*As)[132] = reinterpret_cast<float(*)[132]>(smraw + AS_OFF);
    float (*Bs)[132] = reinterpret_cast<float(*)[132]>(smraw + BS_OFF);
    float4* T = reinterpret_cast<float4*>(smraw + T_OFF);   // 64 rows x 32 f4
    float* na_s = reinterpret_cast<float*>(smraw + NA_OFF); // 128 A-row norms
    float* nb_s = reinterpret_cast<float*>(smraw + NB_OFF); // 128 B-row norms

    const int branch = blockIdx.y;
    const float* emb = branch ? emb2 : emb1;
    float* D2 = g_D2 + (size_t)branch * NN * NN;
    float* bmin = g_bmin + branch * NN * 32;

    // linear -> triangle (bx >= by)
    int l = blockIdx.x;
    int bx = (int)((sqrtf(8.f * (float)l + 1.f) - 1.f) * 0.5f);
    while ((bx + 1) * (bx + 2) / 2 <= l) bx++;
    while (bx * (bx + 1) / 2 > l) bx--;
    int by = l - bx * (bx + 1) / 2;

    const int tid = threadIdx.x;          // 256 threads
    const int tx = tid & 15, ty = tid >> 4;
    const int wid = tid >> 5, lane = tid & 31;
    const int i0 = by * 128, j0 = bx * 128;

    const float4* ea = reinterpret_cast<const float4*>(emb) + (size_t)i0 * 8;
    const float4* eb = reinterpret_cast<const float4*>(emb) + (size_t)j0 * 8;

#pragma unroll
    for (int l2 = 0; l2 < 4; l2++) {
        int lin = l2 * 256 + tid;         // 1024 float4s = 128 rows x 8
        int row = lin >> 3, c4 = lin & 7;
        float4 va = ea[row * 8 + c4];
        As[c4 * 4 + 0][row] = va.x; As[c4 * 4 + 1][row] = va.y;
        As[c4 * 4 + 2][row] = va.z; As[c4 * 4 + 3][row] = va.w;
        float4 vb = eb[row * 8 + c4];
        Bs[c4 * 4 + 0][row] = vb.x; Bs[c4 * 4 + 1][row] = vb.y;
        Bs[c4 * 4 + 2][row] = vb.z; Bs[c4 * 4 + 3][row] = vb.w;
    }

    // in-CTA norms: one per thread (tid<128: A-row tid; else B-row tid-128).
    // Same expression as the old norms_kernel; emb data is L1-hot.
    {
        int row = tid & 127;
        const float4* p = (tid < 128) ? (ea + (size_t)row * 8)
                                      : (eb + (size_t)row * 8);
        float s = 0.f;
#pragma unroll
        for (int i = 0; i < 8; i++) {
            float4 v = p[i];
            s += v.x * v.x + v.y * v.y + v.z * v.z + v.w * v.w;
        }
        if (tid < 128) na_s[row] = s;
        else           nb_s[row] = s;
    }
    __syncthreads();

    float m[8];
#pragma unroll
    for (int r = 0; r < 8; r++) m[r] = 3.4e38f;

#pragma unroll
    for (int p = 0; p < 2; p++) {
        // ---- microGEMM pass p: rows ty*8..+7, cols j0 + p*64 + tx*4..+3 ----
        u64 acc[4][4];                    // [rowpair][col], packed f32x2
#pragma unroll
        for (int rp = 0; rp < 4; rp++)
#pragma unroll
            for (int c = 0; c < 4; c++) acc[rp][c] = 0ull;

#pragma unroll
        for (int k = 0; k < EMBD; k++) {
            float4 alo = *reinterpret_cast<const float4*>(&As[k][ty * 8]);
            float4 ahi = *reinterpret_cast<const float4*>(&As[k][ty * 8 + 4]);
            float4 b4  = *reinterpret_cast<const float4*>(&Bs[k][p * 64 + tx * 4]);
            u64 ap[4] = {pack2(alo.x, alo.y), pack2(alo.z, alo.w),
                         pack2(ahi.x, ahi.y), pack2(ahi.z, ahi.w)};
            u64 bd[4] = {pack2(b4.x, b4.x), pack2(b4.y, b4.y),
                         pack2(b4.z, b4.z), pack2(b4.w, b4.w)};
#pragma unroll
            for (int rp = 0; rp < 4; rp++)
#pragma unroll
                for (int c = 0; c < 4; c++) ffma2(acc[rp][c], ap[rp], bd[c]);
        }

        // ---- epilogue pass p ----
        float na[8], nb[4];
#pragma unroll
        for (int r = 0; r < 8; r++) na[r] = na_s[ty * 8 + r];
#pragma unroll
        for (int c = 0; c < 4; c++) nb[c] = nb_s[p * 64 + tx * 4 + c];

        float o[8][4];
#pragma unroll
        for (int rp = 0; rp < 4; rp++)
#pragma unroll
            for (int c = 0; c < 4; c++)
                unpack2(acc[rp][c], o[2 * rp][c], o[2 * rp + 1][c]);

#pragma unroll
        for (int r = 0; r < 8; r++) {
            int gi = i0 + ty * 8 + r;
#pragma unroll
            for (int c = 0; c < 4; c++) {
                int gj = j0 + p * 64 + tx * 4 + c;
                float d = na[r] + nb[c] - 2.f * o[r][c];
                o[r][c] = (gi == gj) ? 3.4e38f : d;
            }
            *reinterpret_cast<float4*>(D2 + (size_t)gi * NN + j0 + p * 64 + tx * 4) =
                make_float4(o[r][0], o[r][1], o[r][2], o[r][3]);
            m[r] = fminf(m[r],
                         fminf(fminf(o[r][0], o[r][1]), fminf(o[r][2], o[r][3])));
        }

        // ---- mirror staging (off-diagonal): all 256 threads, 64 T-rows ----
        if (bx != by) {
            __syncthreads();              // T free (pass0) / prev readers done
            int s = tx & 7;               // swizzle derived from lc>>2
#pragma unroll
            for (int c = 0; c < 4; c++) {
                int lc = tx * 4 + c;      // T row = local col
                T[lc * 32 + (((ty * 2 + 0) ^ s) & 31)] =
                    make_float4(o[0][c], o[1][c], o[2][c], o[3][c]);
                T[lc * 32 + (((ty * 2 + 1) ^ s) & 31)] =
                    make_float4(o[4][c], o[5][c], o[6][c], o[7][c]);
            }
            __syncthreads();
#pragma unroll
            for (int it = 0; it < 8; it++) {
                int rowl = it * 8 + wid;  // 0..63
                int sw = (rowl >> 2) & 7;
                float4 v = T[rowl * 32 + (lane ^ sw)];
                int gj = j0 + p * 64 + rowl;
                *reinterpret_cast<float4*>(D2 + (size_t)gj * NN + i0 + lane * 4) = v;
                float mm = fminf(fminf(v.x, v.y), fminf(v.z, v.w));
#pragma unroll
                for (int off = 16; off > 0; off >>= 1)
                    mm = fminf(mm, __shfl_xor_sync(FULL, mm, off));
                if (lane == 0)
                    bmin[gj * 32 + by] = mm;
            }
        }
    }

    // ---- final normal-orientation bmin (min over both passes) ----
#pragma unroll
    for (int r = 0; r < 8; r++) {
        float mm = m[r];
#pragma unroll
        for (int off = 8; off > 0; off >>= 1)
            mm = fminf(mm, __shfl_xor_sync(FULL, mm, off));
        if (tx == 0)
            bmin[(i0 + ty * 8 + r) * 32 + bx] = mm;
    }
}

// ---------------------------------------------------------------------------
// Selection. key = orderable(d2)<<32 | (NN-1-j): ties prefer larger j
// (matches stable ascending argsort window semantics of the reference).
// Warp-distributed sorted list; tiles visited ascending-bmin with early
// break and speculative next-tile prefetch (stale-tau superset check).
// ---------------------------------------------------------------------------
__device__ __forceinline__ u32 ord32(float f) {
    u32 u = __float_as_uint(f);
    return u ^ ((u32)((int)u >> 31) | 0x80000000u);
}
__device__ __forceinline__ u64 make_key(float f, int j) {
    return ((u64)ord32(f) << 32) | (u32)(NN - 1 - j);
}
__device__ __forceinline__ float key_d2(u64 k) {
    u32 u = (u32)(k >> 32);
    return (u & 0x80000000u) ? __uint_as_float(u & 0x7fffffffu)
                             : __uint_as_float(~u);
}

__device__ __forceinline__ u64 warp_sort_u64(u64 key, int lane) {
#pragma unroll
    for (int k = 2; k <= 32; k <<= 1) {
#pragma unroll
        for (int j = k >> 1; j > 0; j >>= 1) {
            u64 o = __shfl_xor_sync(FULL, key, j);
            bool up = ((lane & k) == 0) || (k == 32);
            bool lower = ((lane & j) == 0);
            bool take_min = (lower == up);
            u64 mn = (o < key) ? o : key;
            u64 mx = (o < key) ? key : o;
            key = take_min ? mn : mx;
        }
    }
    return key;
}

__device__ __forceinline__ void stream_elem(float d, int t, int e,
                                            u64& list, u64& tau,
                                            float& tau_d2, int lane) {
    unsigned m = __ballot_sync(FULL, d <= tau_d2);   // superset of key<tau
    while (m) {
        int s = __ffs(m) - 1; m &= m - 1;
        float dv = __shfl_sync(FULL, d, s);
        u64 key = make_key(dv, t * 128 + s * 4 + e);
        if (key < tau) {                              // exact check
            unsigned lt = __ballot_sync(FULL, list < key);
            u64 up1 = __shfl_up_sync(FULL, list, 1);
            int pos = __popc(lt);
            if (lane == pos)      list = key;
            else if (lane > pos)  list = up1;
            tau = __shfl_sync(FULL, list, KNN - 1);
            tau_d2 = key_d2(tau);
        }
    }
}

__global__ void knn_select() {
    int gw = blockIdx.x * (blockDim.x >> 5) + (threadIdx.x >> 5);
    int lane = threadIdx.x & 31;
    if (gw >= 2 * NN) return;
    int branch = gw >> 12;                 // gw / NN
    int rowi = gw & (NN - 1);

    const float4* row = reinterpret_cast<const float4*>(
        g_D2 + (size_t)branch * NN * NN + (size_t)rowi * NN);

    // sort (bmin, tile) ascending across lanes
    float bm = g_bmin[(branch * NN + rowi) * 32 + lane];
    u64 skey = warp_sort_u64(((u64)ord32(bm) << 32) | (u32)lane, lane);

    // ---- best tile: init list via bitonic on v.x keys + stream y/z/w ----
    u64 b0 = __shfl_sync(FULL, skey, 0);
    int t0 = (int)(u32)b0;
    float4 v = row[t0 * 32 + lane];
    u64 list = warp_sort_u64(make_key(v.x, t0 * 128 + lane * 4), lane);
    u64 tau = __shfl_sync(FULL, list, KNN - 1);
    float tau_d2 = key_d2(tau);
    stream_elem(v.y, t0, 1, list, tau, tau_d2, lane);
    stream_elem(v.z, t0, 2, list, tau, tau_d2, lane);
    stream_elem(v.w, t0, 3, list, tau, tau_d2, lane);

    // ---- remaining tiles ascending-bmin; prefetch next speculatively ----
    u64 bk = __shfl_sync(FULL, skey, 1);
    int tt = (int)(u32)bk;
    bool valid = key_d2(bk) <= tau_d2;
    float4 vbuf;
    if (valid) vbuf = row[tt * 32 + lane];
    int t = 1;
    while (valid) {
        float4 vc = vbuf;
        int cur = tt;
        if (t + 1 < 32) {                  // speculative prefetch (stale tau)
            bk = __shfl_sync(FULL, skey, t + 1);
            tt = (int)(u32)bk;
            if (key_d2(bk) <= tau_d2) vbuf = row[tt * 32 + lane];
        }
        stream_elem(vc.x, cur, 0, list, tau, tau_d2, lane);
        stream_elem(vc.y, cur, 1, list, tau, tau_d2, lane);
        stream_elem(vc.z, cur, 2, list, tau, tau_d2, lane);
        stream_elem(vc.w, cur, 3, list, tau, tau_d2, lane);
        t++;
        valid = (t < 32) && (key_d2(bk) <= tau_d2);   // updated tau; subset
    }                                                  // of speculative check

    if (lane < KNN) {
        int o = gw * KNN + lane;           // gw == branch*NN + rowi
        g_nbr_idx[o] = NN - 1 - (int)(u32)list;
        g_nbr_d2[o] = key_d2(list);
    }
}

// ---------------------------------------------------------------------------
// Per-query gather + features + MLP. One warp per query. All scattered loads
// issued up-front (both branches), then packed f32x2 warp reductions
// (component order identical to scalar reductions -> bit-exact).
// ---------------------------------------------------------------------------
__device__ __forceinline__ float warp_sum(float v) {
#pragma unroll
    for (int off = 16; off > 0; off >>= 1)
        v += __shfl_xor_sync(FULL, v, off);
    return v;
}
__device__ __forceinline__ u64 warp_sum2(u64 v) {
#pragma unroll
    for (int off = 16; off > 0; off >>= 1)
        v = addf2(v, __shfl_xor_sync(FULL, v, off));
    return v;
}

__global__ void gather_mlp(const int* __restrict__ timev,
                           const int* __restrict__ idx1v,
                           const int* __restrict__ idx2v,
                           const float* __restrict__ residuals,
                           const float* __restrict__ means,
                           const float* __restrict__ stds,
                           const float* __restrict__ W1,
                           const float* __restrict__ b1,
                           const float* __restrict__ Wm,
                           const float* __restrict__ bm,
                           const float* __restrict__ Ws,
                           const float* __restrict__ bs,
                           float* __restrict__ out) {
    int q = (blockIdx.x * blockDim.x + threadIdx.x) >> 5;
    int lane = threadIdx.x & 31;
    if (q >= BQ) return;

    int t = timev[q], a = idx1v[q], c = idx2v[q];
    size_t base = (size_t)t * NN * NN;
    bool act = lane < KNN;

    // stage 1: neighbor tables, both branches
    int j1 = 0, j2 = 0; float d21 = 0.f, d22 = 0.f;
    if (act) {
        int o1 = a * KNN + lane;               // branch 0 (rows by index1)
        int o2 = (NN + c) * KNN + lane;        // branch 1 (rows by index2)
        j1 = g_nbr_idx[o1]; d21 = g_nbr_d2[o1];
        j2 = g_nbr_idx[o2]; d22 = g_nbr_d2[o2];
    }
    // stage 2: all residual gathers + mean/std (issued together)
    float sel1 = 0.f, sel2 = 0.f;
    if (act) {
        sel1 = residuals[base + (size_t)j1 * NN + c];   // f1: column context
        sel2 = residuals[base + (size_t)a * NN + j2];   // f2: row context
    }
    float meanv = means[base + (size_t)a * NN + c];
    float stdv  = stds[base + (size_t)a * NN + c];

    // weights (ALU, overlaps the loads above)
    float w1 = act ? expf(-(sqrtf(fmaxf(d21, 0.f)) + 0.001f)) : 0.f;
    float w2 = act ? expf(-(sqrtf(fmaxf(d22, 0.f)) + 0.001f)) : 0.f;

    // packed reductions: (w*sel, w) and (sel, sel*sel) per branch
    u64 ra1 = warp_sum2(pack2(w1 * sel1, w1));
    u64 rb1 = warp_sum2(pack2(sel1, sel1 * sel1));
    u64 ra2 = warp_sum2(pack2(w2 * sel2, w2));
    u64 rb2 = warp_sum2(pack2(sel2, sel2 * sel2));

    float sw1, wsm1, ss1, s21, sw2, wsm2, ss2, s22;
    unpack2(ra1, sw1, wsm1); unpack2(rb1, ss1, s21);
    unpack2(ra2, sw2, wsm2); unpack2(rb2, ss2, s22);

    float f[8];
    f[0] = sw1 / wsm1;
    f[1] = wsm1;
    f[2] = sqrtf(fmaxf((s21 - ss1 * ss1 / (float)KNN) / (float)(KNN - 1), 0.f));
    f[3] = sw2 / wsm2;
    f[4] = wsm2;
    f[5] = sqrtf(fmaxf((s22 - ss2 * ss2 / (float)KNN) / (float)(KNN - 1), 0.f));
    f[6] = meanv;
    f[7] = stdv;

    float om = 0.f, osum = 0.f;
#pragma unroll
    for (int r = 0; r < 2; r++) {
        int k = lane + r * 32;
        float h = b1[k];
#pragma unroll
        for (int ff = 0; ff < 8; ++ff) h = fmaf(f[ff], W1[k * 8 + ff], h);
        h = fmaxf(h, 0.f);
        om   = fmaf(h, Wm[k], om);
        osum = fmaf(h, Ws[k], osum);
    }
    om = warp_sum(om);
    osum = warp_sum(osum);
    if (lane == 0) {
        out[q]      = om   + bm[0];
        out[BQ + q] = osum + bs[0];
    }
}

// ---------------------------------------------------------------------------
extern "C" void kernel_launch(void* const* d_in, const int* in_sizes, int n_in,
                              void* d_out, int out_size) {
    const int*   timev = (const int*)d_in[0];
    const int*   idx1  = (const int*)d_in[1];
    const int*   idx2  = (const int*)d_in[2];
    const float* resid = (const float*)d_in[3];
    const float* means = (const float*)d_in[4];
    const float* stds  = (const float*)d_in[5];
    const float* emb1  = (const float*)d_in[6];
    const float* emb2  = (const float*)d_in[7];
    const float* W1    = (const float*)d_in[8];
    const float* b1    = (const float*)d_in[9];
    const float* Wm    = (const float*)d_in[10];
    const float* bm    = (const float*)d_in[11];
    const float* Ws    = (const float*)d_in[12];
    const float* bs    = (const float*)d_in[13];
    float* out = (float*)d_out;

    cudaFuncSetAttribute(knn_gemm, cudaFuncAttributeMaxDynamicSharedMemorySize,
                         SMEM_DYN);

    const int TRI = (NN / 128) * (NN / 128 + 1) / 2;   // 528 triangle CTAs
    dim3 gg(TRI, 2);                       // both branches, one launch
    knn_gemm<<<gg, 256, SMEM_DYN>>>(emb1, emb2);

    knn_select<<<2 * NN / 8, 256>>>();     // both branches, one launch

    gather_mlp<<<BQ / 8, 256>>>(timev, idx1, idx2, resid, means, stds,
                                W1, b1, Wm, bm, Ws, bs, out);
}

// round 13
// speedup vs baseline: 1.0631x; 1.0631x over previous
#include <cuda_runtime.h>
#include <math.h>
#include <stdint.h>

#define NN   4096
#define EMBD 32
#define BQ   8192
#define KNN  20
#define FULL 0xffffffffu

typedef unsigned long long u64;
typedef unsigned int u32;

// Scratch (device globals; no allocation in kernel_launch)
__device__ float g_D2[(size_t)2 * NN * NN];    // 2 x 64 MB, one per branch
__device__ float g_bmin[2 * NN * 32];          // per-branch per-row tile mins
__device__ int   g_nbr_idx[2 * NN * KNN];
__device__ float g_nbr_d2[2 * NN * KNN];

// dynamic smem layout for knn_gemm
#define AS_OFF 0
#define BS_OFF 16896                            // 32*132*4
#define T_OFF  33792                            // + 32*132*4
#define NA_OFF 66560                            // + 64*128*4 (T)
#define NB_OFF 67072                            // + 128*4
#define SMEM_DYN 67584                          // + 128*4 = 66 KB

// ---------------------------------------------------------------------------
// packed f32x2 helpers (Blackwell FFMA2 path — PTX only)
// ---------------------------------------------------------------------------
__device__ __forceinline__ u64 pack2(float lo, float hi) {
    u64 r;
    asm("mov.b64 %0, {%1, %2};" : "=l"(r) : "f"(lo), "f"(hi));
    return r;
}
__device__ __forceinline__ void unpack2(u64 v, float& lo, float& hi) {
    asm("mov.b64 {%0, %1}, %2;" : "=f"(lo), "=f"(hi) : "l"(v));
}
__device__ __forceinline__ void ffma2(u64& d, u64 a, u64 b) {
    asm("fma.rn.f32x2 %0, %1, %2, %0;" : "+l"(d) : "l"(a), "l"(b));
}
__device__ __forceinline__ u64 addf2(u64 a, u64 b) {
    u64 r;
    asm("add.rn.f32x2 %0, %1, %2;" : "=l"(r) : "l"(a), "l"(b));
    return r;
}

// ---------------------------------------------------------------------------
// Upper-triangle all-pairs distances, both branches: grid (528, 2).
// Norms computed in-CTA from the ALREADY-STAGED smem tiles (conflict-free
// LDS sweep) — no separate norms kernel, no extra global traffic.
// Two 64-column passes with acc[4][4] packed f32x2 so 3 CTAs/SM fit.
// Mirror tile staged via dedicated swizzled smem region.
// ---------------------------------------------------------------------------
__global__ void __launch_bounds__(256, 3) knn_gemm(const float* __restrict__ emb1,
                                                   const float* __restrict__ emb2) {
    extern __shared__ char smraw[];
    float (*As)[132] = reinterpret_cast<float(*)[132]>(smraw + AS_OFF);
    float (*Bs)[132] = reinterpret_cast<float(*)[132]>(smraw + BS_OFF);
    float4* T = reinterpret_cast<float4*>(smraw + T_OFF);   // 64 rows x 32 f4
    float* na_s = reinterpret_cast<float*>(smraw + NA_OFF); // 128 A-row norms
    float* nb_s = reinterpret_cast<float*>(smraw + NB_OFF); // 128 B-row norms

    const int branch = blockIdx.y;
    const float* emb = branch ? emb2 : emb1;
    float* D2 = g_D2 + (size_t)branch * NN * NN;
    float* bmin = g_bmin + branch * NN * 32;

    // linear -> triangle (bx >= by)
    int l = blockIdx.x;
    int bx = (int)((sqrtf(8.f * (float)l + 1.f) - 1.f) * 0.5f);
    while ((bx + 1) * (bx + 2) / 2 <= l) bx++;
    while (bx * (bx + 1) / 2 > l) bx--;
    int by = l - bx * (bx + 1) / 2;

    const int tid = threadIdx.x;          // 256 threads
    const int tx = tid & 15, ty = tid >> 4;
    const int wid = tid >> 5, lane = tid & 31;
    const int i0 = by * 128, j0 = bx * 128;

    const float4* ea = reinterpret_cast<const float4*>(emb) + (size_t)i0 * 8;
    const float4* eb = reinterpret_cast<const float4*>(emb) + (size_t)j0 * 8;

#pragma unroll
    for (int l2 = 0; l2 < 4; l2++) {
        int lin = l2 * 256 + tid;         // 1024 float4s = 128 rows x 8
        int row = lin >> 3, c4 = lin & 7;
        float4 va = ea[row * 8 + c4];
        As[c4 * 4 + 0][row] = va.x; As[c4 * 4 + 1][row] = va.y;
        As[c4 * 4 + 2][row] = va.z; As[c4 * 4 + 3][row] = va.w;
        float4 vb = eb[row * 8 + c4];
        Bs[c4 * 4 + 0][row] = vb.x; Bs[c4 * 4 + 1][row] = vb.y;
        Bs[c4 * 4 + 2][row] = vb.z; Bs[c4 * 4 + 3][row] = vb.w;
    }
    __syncthreads();

    // in-CTA norms from smem: thread tid<128 -> A-row tid, else B-row tid-128.
    // Fixed row, k sweep: lanes hit consecutive banks at each k -> no
    // conflicts. Float4-group sum order matches the old norms_kernel.
    {
        int row = tid & 127;
        float (*S)[132] = (tid < 128) ? As : Bs;
        float s = 0.f;
#pragma unroll
        for (int g = 0; g < 8; g++) {
            float v0 = S[4 * g + 0][row], v1 = S[4 * g + 1][row];
            float v2 = S[4 * g + 2][row], v3 = S[4 * g + 3][row];
            s += v0 * v0 + v1 * v1 + v2 * v2 + v3 * v3;
        }
        if (tid < 128) na_s[row] = s;
        else           nb_s[row] = s;
    }
    __syncthreads();

    float m[8];
#pragma unroll
    for (int r = 0; r < 8; r++) m[r] = 3.4e38f;

#pragma unroll
    for (int p = 0; p < 2; p++) {
        // ---- microGEMM pass p: rows ty*8..+7, cols j0 + p*64 + tx*4..+3 ----
        u64 acc[4][4];                    // [rowpair][col], packed f32x2
#pragma unroll
        for (int rp = 0; rp < 4; rp++)
#pragma unroll
            for (int c = 0; c < 4; c++) acc[rp][c] = 0ull;

#pragma unroll
        for (int k = 0; k < EMBD; k++) {
            // A row-pairs loaded directly as 64-bit LDS (no pack MOVs)
            u64 ap[4];
#pragma unroll
            for (int i = 0; i < 4; i++)
                ap[i] = *reinterpret_cast<const u64*>(&As[k][ty * 8 + 2 * i]);
            float4 b4 = *reinterpret_cast<const float4*>(&Bs[k][p * 64 + tx * 4]);
            u64 bd[4] = {pack2(b4.x, b4.x), pack2(b4.y, b4.y),
                         pack2(b4.z, b4.z), pack2(b4.w, b4.w)};
#pragma unroll
            for (int rp = 0; rp < 4; rp++)
#pragma unroll
                for (int c = 0; c < 4; c++) ffma2(acc[rp][c], ap[rp], bd[c]);
        }

        // ---- epilogue pass p ----
        float na[8], nb[4];
#pragma unroll
        for (int r = 0; r < 8; r++) na[r] = na_s[ty * 8 + r];
#pragma unroll
        for (int c = 0; c < 4; c++) nb[c] = nb_s[p * 64 + tx * 4 + c];

        float o[8][4];
#pragma unroll
        for (int rp = 0; rp < 4; rp++)
#pragma unroll
            for (int c = 0; c < 4; c++)
                unpack2(acc[rp][c], o[2 * rp][c], o[2 * rp + 1][c]);

#pragma unroll
        for (int r = 0; r < 8; r++) {
            int gi = i0 + ty * 8 + r;
#pragma unroll
            for (int c = 0; c < 4; c++) {
                int gj = j0 + p * 64 + tx * 4 + c;
                float d = na[r] + nb[c] - 2.f * o[r][c];
                o[r][c] = (gi == gj) ? 3.4e38f : d;
            }
            *reinterpret_cast<float4*>(D2 + (size_t)gi * NN + j0 + p * 64 + tx * 4) =
                make_float4(o[r][0], o[r][1], o[r][2], o[r][3]);
            m[r] = fminf(m[r],
                         fminf(fminf(o[r][0], o[r][1]), fminf(o[r][2], o[r][3])));
        }

        // ---- mirror staging (off-diagonal): all 256 threads, 64 T-rows ----
        if (bx != by) {
            __syncthreads();              // T free (pass0) / prev readers done
            int s = tx & 7;               // swizzle derived from lc>>2
#pragma unroll
            for (int c = 0; c < 4; c++) {
                int lc = tx * 4 + c;      // T row = local col
                T[lc * 32 + (((ty * 2 + 0) ^ s) & 31)] =
                    make_float4(o[0][c], o[1][c], o[2][c], o[3][c]);
                T[lc * 32 + (((ty * 2 + 1) ^ s) & 31)] =
                    make_float4(o[4][c], o[5][c], o[6][c], o[7][c]);
            }
            __syncthreads();
#pragma unroll
            for (int it = 0; it < 8; it++) {
                int rowl = it * 8 + wid;  // 0..63
                int sw = (rowl >> 2) & 7;
                float4 v = T[rowl * 32 + (lane ^ sw)];
                int gj = j0 + p * 64 + rowl;
                *reinterpret_cast<float4*>(D2 + (size_t)gj * NN + i0 + lane * 4) = v;
                float mm = fminf(fminf(v.x, v.y), fminf(v.z, v.w));
#pragma unroll
                for (int off = 16; off > 0; off >>= 1)
                    mm = fminf(mm, __shfl_xor_sync(FULL, mm, off));
                if (lane == 0)
                    bmin[gj * 32 + by] = mm;
            }
        }
    }

    // ---- final normal-orientation bmin (min over both passes) ----
#pragma unroll
    for (int r = 0; r < 8; r++) {
        float mm = m[r];
#pragma unroll
        for (int off = 8; off > 0; off >>= 1)
            mm = fminf(mm, __shfl_xor_sync(FULL, mm, off));
        if (tx == 0)
            bmin[(i0 + ty * 8 + r) * 32 + bx] = mm;
    }
}

// ---------------------------------------------------------------------------
// Selection. key = orderable(d2)<<32 | (NN-1-j): ties prefer larger j
// (matches stable ascending argsort window semantics of the reference).
// Warp-distributed sorted list; tiles visited ascending-bmin with early
// break and speculative next-tile prefetch (stale-tau superset check).
// ---------------------------------------------------------------------------
__device__ __forceinline__ u32 ord32(float f) {
    u32 u = __float_as_uint(f);
    return u ^ ((u32)((int)u >> 31) | 0x80000000u);
}
__device__ __forceinline__ u64 make_key(float f, int j) {
    return ((u64)ord32(f) << 32) | (u32)(NN - 1 - j);
}
__device__ __forceinline__ float key_d2(u64 k) {
    u32 u = (u32)(k >> 32);
    return (u & 0x80000000u) ? __uint_as_float(u & 0x7fffffffu)
                             : __uint_as_float(~u);
}

__device__ __forceinline__ u64 warp_sort_u64(u64 key, int lane) {
#pragma unroll
    for (int k = 2; k <= 32; k <<= 1) {
#pragma unroll
        for (int j = k >> 1; j > 0; j >>= 1) {
            u64 o = __shfl_xor_sync(FULL, key, j);
            bool up = ((lane & k) == 0) || (k == 32);
            bool lower = ((lane & j) == 0);
            bool take_min = (lower == up);
            u64 mn = (o < key) ? o : key;
            u64 mx = (o < key) ? key : o;
            key = take_min ? mn : mx;
        }
    }
    return key;
}

__device__ __forceinline__ void stream_elem(float d, int t, int e,
                                            u64& list, u64& tau,
                                            float& tau_d2, int lane) {
    unsigned m = __ballot_sync(FULL, d <= tau_d2);   // superset of key<tau
    while (m) {
        int s = __ffs(m) - 1; m &= m - 1;
        float dv = __shfl_sync(FULL, d, s);
        u64 key = make_key(dv, t * 128 + s * 4 + e);
        if (key < tau) {                              // exact check
            unsigned lt = __ballot_sync(FULL, list < key);
            u64 up1 = __shfl_up_sync(FULL, list, 1);
            int pos = __popc(lt);
            if (lane == pos)      list = key;
            else if (lane > pos)  list = up1;
            tau = __shfl_sync(FULL, list, KNN - 1);
            tau_d2 = key_d2(tau);
        }
    }
}

__global__ void knn_select() {
    int gw = blockIdx.x * (blockDim.x >> 5) + (threadIdx.x >> 5);
    int lane = threadIdx.x & 31;
    if (gw >= 2 * NN) return;
    int branch = gw >> 12;                 // gw / NN
    int rowi = gw & (NN - 1);

    const float4* row = reinterpret_cast<const float4*>(
        g_D2 + (size_t)branch * NN * NN + (size_t)rowi * NN);

    // sort (bmin, tile) ascending across lanes
    float bm = g_bmin[(branch * NN + rowi) * 32 + lane];
    u64 skey = warp_sort_u64(((u64)ord32(bm) << 32) | (u32)lane, lane);

    // ---- best tile: init list via bitonic on v.x keys + stream y/z/w ----
    u64 b0 = __shfl_sync(FULL, skey, 0);
    int t0 = (int)(u32)b0;
    float4 v = row[t0 * 32 + lane];
    u64 list = warp_sort_u64(make_key(v.x, t0 * 128 + lane * 4), lane);
    u64 tau = __shfl_sync(FULL, list, KNN - 1);
    float tau_d2 = key_d2(tau);
    stream_elem(v.y, t0, 1, list, tau, tau_d2, lane);
    stream_elem(v.z, t0, 2, list, tau, tau_d2, lane);
    stream_elem(v.w, t0, 3, list, tau, tau_d2, lane);

    // ---- remaining tiles ascending-bmin; prefetch next speculatively ----
    u64 bk = __shfl_sync(FULL, skey, 1);
    int tt = (int)(u32)bk;
    bool valid = key_d2(bk) <= tau_d2;
    float4 vbuf;
    if (valid) vbuf = row[tt * 32 + lane];
    int t = 1;
    while (valid) {
        float4 vc = vbuf;
        int cur = tt;
        if (t + 1 < 32) {                  // speculative prefetch (stale tau)
            bk = __shfl_sync(FULL, skey, t + 1);
            tt = (int)(u32)bk;
            if (key_d2(bk) <= tau_d2) vbuf = row[tt * 32 + lane];
        }
        stream_elem(vc.x, cur, 0, list, tau, tau_d2, lane);
        stream_elem(vc.y, cur, 1, list, tau, tau_d2, lane);
        stream_elem(vc.z, cur, 2, list, tau, tau_d2, lane);
        stream_elem(vc.w, cur, 3, list, tau, tau_d2, lane);
        t++;
        valid = (t < 32) && (key_d2(bk) <= tau_d2);   // updated tau; subset
    }                                                  // of speculative check

    if (lane < KNN) {
        int o = gw * KNN + lane;           // gw == branch*NN + rowi
        g_nbr_idx[o] = NN - 1 - (int)(u32)list;
        g_nbr_d2[o] = key_d2(list);
    }
}

// ---------------------------------------------------------------------------
// Per-query gather + features + MLP. One warp per query. All scattered loads
// issued up-front (both branches), then packed f32x2 warp reductions
// (component order identical to scalar reductions -> bit-exact).
// ---------------------------------------------------------------------------
__device__ __forceinline__ float warp_sum(float v) {
#pragma unroll
    for (int off = 16; off > 0; off >>= 1)
        v += __shfl_xor_sync(FULL, v, off);
    return v;
}
__device__ __forceinline__ u64 warp_sum2(u64 v) {
#pragma unroll
    for (int off = 16; off > 0; off >>= 1)
        v = addf2(v, __shfl_xor_sync(FULL, v, off));
    return v;
}

__global__ void gather_mlp(const int* __restrict__ timev,
                           const int* __restrict__ idx1v,
                           const int* __restrict__ idx2v,
                           const float* __restrict__ residuals,
                           const float* __restrict__ means,
                           const float* __restrict__ stds,
                           const float* __restrict__ W1,
                           const float* __restrict__ b1,
                           const float* __restrict__ Wm,
                           const float* __restrict__ bm,
                           const float* __restrict__ Ws,
                           const float* __restrict__ bs,
                           float* __restrict__ out) {
    int q = (blockIdx.x * blockDim.x + threadIdx.x) >> 5;
    int lane = threadIdx.x & 31;
    if (q >= BQ) return;

    int t = timev[q], a = idx1v[q], c = idx2v[q];
    size_t base = (size_t)t * NN * NN;
    bool act = lane < KNN;

    // stage 1: neighbor tables, both branches
    int j1 = 0, j2 = 0; float d21 = 0.f, d22 = 0.f;
    if (act) {
        int o1 = a * KNN + lane;               // branch 0 (rows by index1)
        int o2 = (NN + c) * KNN + lane;        // branch 1 (rows by index2)
        j1 = g_nbr_idx[o1]; d21 = g_nbr_d2[o1];
        j2 = g_nbr_idx[o2]; d22 = g_nbr_d2[o2];
    }
    // stage 2: all residual gathers + mean/std (issued together)
    float sel1 = 0.f, sel2 = 0.f;
    if (act) {
        sel1 = residuals[base + (size_t)j1 * NN + c];   // f1: column context
        sel2 = residuals[base + (size_t)a * NN + j2];   // f2: row context
    }
    float meanv = means[base + (size_t)a * NN + c];
    float stdv  = stds[base + (size_t)a * NN + c];

    // weights (ALU, overlaps the loads above)
    float w1 = act ? expf(-(sqrtf(fmaxf(d21, 0.f)) + 0.001f)) : 0.f;
    float w2 = act ? expf(-(sqrtf(fmaxf(d22, 0.f)) + 0.001f)) : 0.f;

    // packed reductions: (w*sel, w) and (sel, sel*sel) per branch
    u64 ra1 = warp_sum2(pack2(w1 * sel1, w1));
    u64 rb1 = warp_sum2(pack2(sel1, sel1 * sel1));
    u64 ra2 = warp_sum2(pack2(w2 * sel2, w2));
    u64 rb2 = warp_sum2(pack2(sel2, sel2 * sel2));

    float sw1, wsm1, ss1, s21, sw2, wsm2, ss2, s22;
    unpack2(ra1, sw1, wsm1); unpack2(rb1, ss1, s21);
    unpack2(ra2, sw2, wsm2); unpack2(rb2, ss2, s22);

    float f[8];
    f[0] = sw1 / wsm1;
    f[1] = wsm1;
    f[2] = sqrtf(fmaxf((s21 - ss1 * ss1 / (float)KNN) / (float)(KNN - 1), 0.f));
    f[3] = sw2 / wsm2;
    f[4] = wsm2;
    f[5] = sqrtf(fmaxf((s22 - ss2 * ss2 / (float)KNN) / (float)(KNN - 1), 0.f));
    f[6] = meanv;
    f[7] = stdv;

    float om = 0.f, osum = 0.f;
#pragma unroll
    for (int r = 0; r < 2; r++) {
        int k = lane + r * 32;
        float h = b1[k];
#pragma unroll
        for (int ff = 0; ff < 8; ++ff) h = fmaf(f[ff], W1[k * 8 + ff], h);
        h = fmaxf(h, 0.f);
        om   = fmaf(h, Wm[k], om);
        osum = fmaf(h, Ws[k], osum);
    }
    om = warp_sum(om);
    osum = warp_sum(osum);
    if (lane == 0) {
        out[q]      = om   + bm[0];
        out[BQ + q] = osum + bs[0];
    }
}

// ---------------------------------------------------------------------------
extern "C" void kernel_launch(void* const* d_in, const int* in_sizes, int n_in,
                              void* d_out, int out_size) {
    const int*   timev = (const int*)d_in[0];
    const int*   idx1  = (const int*)d_in[1];
    const int*   idx2  = (const int*)d_in[2];
    const float* resid = (const float*)d_in[3];
    const float* means = (const float*)d_in[4];
    const float* stds  = (const float*)d_in[5];
    const float* emb1  = (const float*)d_in[6];
    const float* emb2  = (const float*)d_in[7];
    const float* W1    = (const float*)d_in[8];
    const float* b1    = (const float*)d_in[9];
    const float* Wm    = (const float*)d_in[10];
    const float* bm    = (const float*)d_in[11];
    const float* Ws    = (const float*)d_in[12];
    const float* bs    = (const float*)d_in[13];
    float* out = (float*)d_out;

    cudaFuncSetAttribute(knn_gemm, cudaFuncAttributeMaxDynamicSharedMemorySize,
                         SMEM_DYN);

    const int TRI = (NN / 128) * (NN / 128 + 1) / 2;   // 528 triangle CTAs
    dim3 gg(TRI, 2);                       // both branches, one launch
    knn_gemm<<<gg, 256, SMEM_DYN>>>(emb1, emb2);

    knn_select<<<2 * NN / 8, 256>>>();     // both branches, one launch

    gather_mlp<<<BQ / 8, 256>>>(timev, idx1, idx2, resid, means, stds,
                                W1, b1, Wm, bm, Ws, bs, out);
}